// round 2
// baseline (speedup 1.0000x reference)
#include <cuda_runtime.h>

// HitTheMiddleModel: per-row physics step + 1e-10 * (x @ W^T + b).
// B = 8388608 rows, 3 floats in / 3 floats out per row. Pure HBM-streaming.
// Each thread handles 4 rows = 12 floats = 3x float4 (16B aligned since
// thread stride is 48 bytes). Fully coalesced loads and stores.

#define B_ROWS 8388608
#define ROWS_PER_THREAD 4
#define THREADS_PER_BLOCK 256

__device__ __forceinline__ void row_compute(
    float x0, float x1, float x2,
    float w00, float w01, float w02,
    float w10, float w11, float w12,
    float w20, float w21, float w22,
    float b0, float b1, float b2,
    float& o0, float& o1, float& o2)
{
    float vel = x1 + x2;
    float pos = x0 + vel;
    bool hit = (pos > 10.0f) || (pos < -10.0f);
    vel = hit ? -vel : vel;
    pos = fminf(fmaxf(pos, -10.0f), 10.0f);
    float reward = -pos * pos;

    float y0 = fmaf(x0, w00, fmaf(x1, w01, fmaf(x2, w02, b0)));
    float y1 = fmaf(x0, w10, fmaf(x1, w11, fmaf(x2, w12, b1)));
    float y2 = fmaf(x0, w20, fmaf(x1, w21, fmaf(x2, w22, b2)));

    o0 = fmaf(1e-10f, y0, pos);
    o1 = fmaf(1e-10f, y1, vel);
    o2 = fmaf(1e-10f, y2, reward);
}

__global__ void __launch_bounds__(THREADS_PER_BLOCK)
hit_middle_kernel(const float4* __restrict__ x4,
                  const float* __restrict__ W,
                  const float* __restrict__ bb,
                  float4* __restrict__ out4)
{
    const unsigned t = blockIdx.x * THREADS_PER_BLOCK + threadIdx.x;

    // Broadcast loads: hit L1, every thread same address.
    const float w00 = W[0], w01 = W[1], w02 = W[2];
    const float w10 = W[3], w11 = W[4], w12 = W[5];
    const float w20 = W[6], w21 = W[7], w22 = W[8];
    const float b0 = bb[0], b1 = bb[1], b2 = bb[2];

    // 4 rows = 12 floats = 3 float4 (thread byte offset 48*t, 16B aligned)
    const unsigned base = 3u * t;
    float4 a = x4[base + 0];
    float4 c = x4[base + 1];
    float4 d = x4[base + 2];

    // rows: (a.x,a.y,a.z) (a.w,c.x,c.y) (c.z,c.w,d.x) (d.y,d.z,d.w)
    float4 oa, oc, od;
    row_compute(a.x, a.y, a.z, w00,w01,w02,w10,w11,w12,w20,w21,w22, b0,b1,b2,
                oa.x, oa.y, oa.z);
    row_compute(a.w, c.x, c.y, w00,w01,w02,w10,w11,w12,w20,w21,w22, b0,b1,b2,
                oa.w, oc.x, oc.y);
    row_compute(c.z, c.w, d.x, w00,w01,w02,w10,w11,w12,w20,w21,w22, b0,b1,b2,
                oc.z, oc.w, od.x);
    row_compute(d.y, d.z, d.w, w00,w01,w02,w10,w11,w12,w20,w21,w22, b0,b1,b2,
                od.y, od.z, od.w);

    out4[base + 0] = oa;
    out4[base + 1] = oc;
    out4[base + 2] = od;
}

extern "C" void kernel_launch(void* const* d_in, const int* in_sizes, int n_in,
                              void* d_out, int out_size)
{
    const float4* x4 = (const float4*)d_in[0];   // x [B,3] fp32
    const float*  W  = (const float*)d_in[1];    // W [3,3]
    const float*  bb = (const float*)d_in[2];    // b [3]
    float4* out4 = (float4*)d_out;               // [B,3] fp32

    const int total_threads = B_ROWS / ROWS_PER_THREAD;          // 2097152
    const int blocks = total_threads / THREADS_PER_BLOCK;        // 8192

    hit_middle_kernel<<<blocks, THREADS_PER_BLOCK>>>(x4, W, bb, out4);
}